// round 14
// baseline (speedup 1.0000x reference)
#include <cuda_runtime.h>
#include <cuda_fp16.h>
#include <cstdint>

// ---------------- problem constants ----------------
#define B_    8
#define HDIM  112
#define WDIM  112
#define CDIM  384
#define NHEAD 12
#define HD    32
#define WS    7
#define SSH   3
#define NTOK  49
#define NWH   16
#define NWW   16
#define NWIN  256
#define BW    (B_ * NWIN)          // 2048 windows
#define MROWS (BW * NTOK)          // 100352
#define QKVN  (3 * CDIM)           // 1152
#define BSTRIDE 2432

// GEMM tiling: 128x128 CTA tile, 32x64 warp tiles (4Mx2N), 3-stage cp.async
#define TM   128
#define TN   128
#define KC   64
#define NCH  (CDIM / KC)           // 6
#define ROWB 144
#define TILEB (128 * ROWB)         // 18432
#define STAGEB (2 * TILEB)         // 36864
#define NSTAGE 3
#define SMEM_SZ (NSTAGE * STAGEB)  // 110592

// prep fusion ranges
#define NB_BIAS (NHEAD * NTOK * NTOK)    // 28812
#define NW_QKV  (QKVN * CDIM)            // 442368
#define NW_PROJ (CDIM * CDIM)            // 147456
#define PREP_TOTAL (NB_BIAS + NW_QKV + NW_PROJ)

// attention n-tiles: 7 tiles x 8 cols = 56 >= 49 valid cols
#define NFT  7

// ---------------- scratch ----------------
__device__ __half gQh[(size_t)BW * NHEAD * NTOK * HD];
__device__ __half gKh[(size_t)BW * NHEAD * NTOK * HD];
__device__ __half gVh[(size_t)BW * NHEAD * NTOK * HD];
__device__ __half gXh[(size_t)MROWS * CDIM];
__device__ __half gOh[(size_t)MROWS * CDIM];
__device__ __half gWh[(size_t)QKVN * CDIM];
__device__ __half gPh[(size_t)CDIM * CDIM];
__device__ __half gBiasH[NHEAD * BSTRIDE];   // zero-init; tail stays 0

// ---------------- helpers ----------------
#define CP_ASYNC16(dst, src) \
    asm volatile("cp.async.cg.shared.global [%0], [%1], 16;" :: "r"(dst), "l"(src))
#define CP_COMMIT() asm volatile("cp.async.commit_group;" ::: "memory")
#define CP_WAIT(n)  asm volatile("cp.async.wait_group %0;" :: "n"(n) : "memory")

__device__ __forceinline__ uint32_t smem_u32(const void* p) {
    uint32_t a;
    asm("{ .reg .u64 t; cvta.to.shared.u64 t, %1; cvt.u32.u64 %0, t; }" : "=r"(a) : "l"(p));
    return a;
}
__device__ __forceinline__ void ldsm_x4(uint32_t* r, uint32_t addr) {
    asm volatile("ldmatrix.sync.aligned.m8n8.x4.shared.b16 {%0,%1,%2,%3}, [%4];"
                 : "=r"(r[0]), "=r"(r[1]), "=r"(r[2]), "=r"(r[3]) : "r"(addr));
}
__device__ __forceinline__ void ldsm_x4_trans(uint32_t* r, uint32_t addr) {
    asm volatile("ldmatrix.sync.aligned.m8n8.x4.trans.shared.b16 {%0,%1,%2,%3}, [%4];"
                 : "=r"(r[0]), "=r"(r[1]), "=r"(r[2]), "=r"(r[3]) : "r"(addr));
}
__device__ __forceinline__ void mma16816(float* c, const uint32_t* a, const uint32_t* b) {
    asm volatile(
        "mma.sync.aligned.m16n8k16.row.col.f32.f16.f16.f32 "
        "{%0,%1,%2,%3}, {%4,%5,%6,%7}, {%8,%9}, {%0,%1,%2,%3};"
        : "+f"(c[0]), "+f"(c[1]), "+f"(c[2]), "+f"(c[3])
        : "r"(a[0]), "r"(a[1]), "r"(a[2]), "r"(a[3]), "r"(b[0]), "r"(b[1]));
}
__device__ __forceinline__ uint32_t h2pack(float a, float b) {
    __half2 h = __floats2half2_rn(a, b);
    return *reinterpret_cast<uint32_t*>(&h);
}

// ---------------- shift/window row mapping ----------------
__device__ __forceinline__ int src_row(int m) {
    int w  = m / NTOK;
    int n  = m - w * NTOK;
    int b  = w / NWIN;
    int wi = w - b * NWIN;
    int wy = wi / NWW;
    int wx = wi - wy * NWW;
    int ty = n / WS;
    int tx = n - ty * WS;
    int sy = wy * WS + ty;
    int sx = wx * WS + tx;
    int oy = sy + SSH; if (oy >= HDIM) oy -= HDIM;
    int ox = sx + SSH; if (ox >= WDIM) ox -= WDIM;
    return (b * HDIM + oy) * WDIM + ox;
}

// ---------------- prep: fused bias + both weight converts ----------------
__global__ __launch_bounds__(256) void prep_all(const float* __restrict__ rpt,
                                                const float* __restrict__ qkv_w,
                                                const float* __restrict__ proj_w) {
    int t = blockIdx.x * blockDim.x + threadIdx.x;
    if (t < NB_BIAS) {
        int h = t / (NTOK * NTOK);
        int r = t - h * (NTOK * NTOK);
        int i = r / NTOK;
        int j = r - i * NTOK;
        int ci = 13 * (i / 7) + (i % 7);
        int jr = 48 - j;
        int cj = 13 * (jr / 7) + (jr % 7);
        gBiasH[h * BSTRIDE + r] = __float2half_rn(rpt[(ci + cj) * NHEAD + h]);
    } else if (t < NB_BIAS + NW_QKV) {
        int i = t - NB_BIAS;
        int n = i / CDIM;
        int k = i - n * CDIM;
        gWh[i] = __float2half_rn(qkv_w[(size_t)k * QKVN + n]);
    } else if (t < PREP_TOTAL) {
        int i = t - NB_BIAS - NW_QKV;
        int n = i / CDIM;
        int k = i - n * CDIM;
        gPh[i] = __float2half_rn(proj_w[(size_t)k * CDIM + n]);
    }
}

__global__ __launch_bounds__(256) void gather_h(const float* __restrict__ x) {
    int t = blockIdx.x * blockDim.x + threadIdx.x;
    if (t >= MROWS * (CDIM / 4)) return;
    int m = t / (CDIM / 4);
    int q = t - m * (CDIM / 4);
    float4 v = *(const float4*)(x + (size_t)src_row(m) * CDIM + q * 4);
    *(uint2*)(gXh + (size_t)m * CDIM + q * 4) =
        make_uint2(h2pack(v.x, v.y), h2pack(v.z, v.w));
}

// ---------------- HMMA GEMM: C[m,n] = sum_k A[m,k]*B[n,k] + bias[n] --------------
__device__ __forceinline__ void load_stage(uint32_t sbuf, int tid,
        const __half* A, const __half* Bm, int m0, int n0, int k0) {
#pragma unroll
    for (int i = 0; i < 8; ++i) {
        int q    = tid + i * 256;
        int tile = q >> 10;
        int idx  = q & 1023;
        int r    = idx >> 3;
        int c    = idx & 7;
        const __half* srcp = (tile == 0)
            ? A  + (size_t)(m0 + r) * CDIM + k0 + c * 8
            : Bm + (size_t)(n0 + r) * CDIM + k0 + c * 8;
        uint32_t dst = sbuf + tile * TILEB + r * ROWB + c * 16;
        CP_ASYNC16(dst, srcp);
    }
}

__global__ __launch_bounds__(256, 2) void mma_gemm(
        const __half* __restrict__ A, const __half* __restrict__ Bm,
        const float* __restrict__ bias, float* __restrict__ outp, int mode) {
    extern __shared__ char smem[];
    uint32_t sb = smem_u32(smem);

    int tid  = threadIdx.x;
    int wid  = tid >> 5;
    int lane = tid & 31;
    int wm   = wid & 3;
    int wn   = wid >> 2;
    int n0   = blockIdx.x * TN;
    int m0   = blockIdx.y * TM;

    float acc[2][8][4];
#pragma unroll
    for (int i = 0; i < 2; ++i)
#pragma unroll
        for (int j = 0; j < 8; ++j)
#pragma unroll
            for (int k = 0; k < 4; ++k) acc[i][j][k] = 0.f;

    load_stage(sb, tid, A, Bm, m0, n0, 0);
    CP_COMMIT();
    load_stage(sb + STAGEB, tid, A, Bm, m0, n0, KC);
    CP_COMMIT();
    load_stage(sb + 2 * STAGEB, tid, A, Bm, m0, n0, 2 * KC);
    CP_COMMIT();

    int l8  = lane & 7;
    int sel = lane >> 3;
    int g   = lane >> 2;
    int cq  = lane & 3;

#pragma unroll 1
    for (int s = 0; s < NCH; ++s) {
        if (s < NCH - 2)       { CP_WAIT(2); }
        else if (s == NCH - 2) { CP_WAIT(1); }
        else                   { CP_WAIT(0); }
        __syncthreads();
        int bufi = s % NSTAGE;
        uint32_t aBase = sb + bufi * STAGEB;
        uint32_t bBase = aBase + TILEB;

#pragma unroll
        for (int ks = 0; ks < 4; ++ks) {
            int kb = ks * 32;
            uint32_t af[2][4];
#pragma unroll
            for (int mf = 0; mf < 2; ++mf) {
                uint32_t addr = aBase
                    + (wm * 32 + mf * 16 + (sel & 1) * 8 + l8) * ROWB
                    + kb + (sel >> 1) * 16;
                ldsm_x4(af[mf], addr);
            }
            uint32_t bf[8][2];
#pragma unroll
            for (int np = 0; np < 4; ++np) {
                uint32_t r4[4];
                uint32_t addr = bBase
                    + (wn * 64 + np * 16 + (sel >> 1) * 8 + l8) * ROWB
                    + kb + (sel & 1) * 16;
                ldsm_x4(r4, addr);
                bf[np * 2 + 0][0] = r4[0]; bf[np * 2 + 0][1] = r4[1];
                bf[np * 2 + 1][0] = r4[2]; bf[np * 2 + 1][1] = r4[3];
            }
#pragma unroll
            for (int mf = 0; mf < 2; ++mf)
#pragma unroll
                for (int nf = 0; nf < 8; ++nf)
                    mma16816(acc[mf][nf], af[mf], bf[nf]);
        }
        __syncthreads();
        if (s + 3 < NCH) {
            load_stage(sb + bufi * STAGEB, tid, A, Bm, m0, n0, (s + 3) * KC);
            CP_COMMIT();
        }
    }

    const float qscale = 0.17677669529663689f;
#pragma unroll
    for (int mf = 0; mf < 2; ++mf) {
#pragma unroll
        for (int nf = 0; nf < 8; ++nf) {
            int cn   = n0 + wn * 64 + nf * 8 + cq * 2;
            int row0 = m0 + wm * 32 + mf * 16 + g;
            float2 bb = *(const float2*)(bias + cn);
            float v00 = acc[mf][nf][0] + bb.x, v01 = acc[mf][nf][1] + bb.y;
            float v10 = acc[mf][nf][2] + bb.x, v11 = acc[mf][nf][3] + bb.y;
            if (mode == 0) {
                int t   = cn / CDIM;
                int rem = cn - t * CDIM;
                int hh  = rem >> 5;
                int d   = rem & 31;
                __half* basep = (t == 0) ? gQh : (t == 1) ? gKh : gVh;
                float sc = (t == 0) ? qscale : 1.0f;
#pragma unroll
                for (int rr = 0; rr < 2; ++rr) {
                    int m  = row0 + rr * 8;
                    int w  = m / NTOK;
                    int nn = m - w * NTOK;
                    uint32_t hv = (rr == 0) ? h2pack(v00 * sc, v01 * sc)
                                            : h2pack(v10 * sc, v11 * sc);
                    *(uint32_t*)(basep + ((size_t)(w * NHEAD + hh) * NTOK + nn) * HD + d) = hv;
                }
            } else {
#pragma unroll
                for (int rr = 0; rr < 2; ++rr) {
                    int m = row0 + rr * 8;
                    int orow = src_row(m);
                    *(float2*)(outp + (size_t)orow * CDIM + cn) =
                        (rr == 0) ? make_float2(v00, v01) : make_float2(v10, v11);
                }
            }
        }
    }
}

// ---------------- attention: HMMA, 7 n-tiles, no Q/K pad-zeroing ----------------
#define QSTR 40      // Qs/Ks/Vs row stride in halfs
#define NPADR 64

__global__ __launch_bounds__(64) void attn_mma() {
    __shared__ __half Qs[NPADR * QSTR];
    __shared__ __half Ks[NPADR * QSTR];
    __shared__ __half Vs[NPADR * QSTR];
    __shared__ __align__(16) __half Bs[2432];
    __shared__ int    rcnt[NPADR];

    int bid = blockIdx.x;
    int w   = bid / NHEAD;
    int h   = bid - w * NHEAD;
    int tid  = threadIdx.x;
    int wi   = tid >> 5;
    int lane = tid & 31;
    int g    = lane >> 2;
    int cq   = lane & 3;
    int l8   = lane & 7;
    int sel  = lane >> 3;

    size_t base = (size_t)(w * NHEAD + h) * NTOK * HD;
    const uint4* q4 = (const uint4*)(gQh + base);
    const uint4* k4 = (const uint4*)(gKh + base);
    const uint4* v4 = (const uint4*)(gVh + base);

    // ---- zero V pad rows only (P cols >=49 have prob exactly 0; 0*garbage must
    //      not be NaN, so V pads must be finite). Q/K pads need no zeroing:
    //      garbage K cols are overwritten with -1e30 pre-exp; garbage Q rows are
    //      never stored and their reductions stay within their own quads. ----
    {
        uint32_t* vz = (uint32_t*)(Vs + NTOK * QSTR);
#pragma unroll
        for (int i = 0; i < 5; ++i) {
            int idx = tid + i * 64;
            if (idx < 300) vz[idx] = 0;
        }
    }
    __syncthreads();

    // ---- fills (49 valid rows, vectorized) ----
#pragma unroll
    for (int i = 0; i < 4; ++i) {
        int idx = tid + i * 64;
        if (idx < NTOK * 4) {
            int r = idx >> 2, c = idx & 3;
            *(uint4*)(Qs + r * QSTR + c * 8) = q4[idx];
            *(uint4*)(Ks + r * QSTR + c * 8) = k4[idx];
            *(uint4*)(Vs + r * QSTR + c * 8) = v4[idx];
        }
    }
    const uint4* b4 = (const uint4*)(gBiasH + h * BSTRIDE);
#pragma unroll
    for (int i = 0; i < 5; ++i) {
        int idx = tid + i * 64;
        if (idx < 304) ((uint4*)Bs)[idx] = b4[idx];
    }
    if (tid < NPADR) {
        int r = 0;
        if (tid < NTOK) {
            int wpos = w % NWIN;
            int wy = wpos / NWW, wx = wpos - wy * NWW;
            int ty = tid / WS, tx = tid - ty * WS;
            int sy = wy * WS + ty, sx = wx * WS + tx;
            int idh = (sy < HDIM - WS) ? 0 : (sy < HDIM - SSH) ? 1 : 2;
            int idw = (sx < WDIM - WS) ? 0 : (sx < WDIM - SSH) ? 1 : 2;
            r = idh * 3 + idw;
        }
        rcnt[tid] = r;
    }
    __syncthreads();

    uint32_t qsb = smem_u32(Qs);
    uint32_t ksb = smem_u32(Ks);
    uint32_t vsb = smem_u32(Vs);

    float s[2][NFT][4];
#pragma unroll
    for (int i = 0; i < 2; ++i)
#pragma unroll
        for (int j = 0; j < NFT; ++j)
#pragma unroll
            for (int k = 0; k < 4; ++k) s[i][j][k] = 0.f;

#pragma unroll
    for (int ks = 0; ks < 2; ++ks) {
        int kb = ks * 32;
        uint32_t af[2][4];
#pragma unroll
        for (int mf = 0; mf < 2; ++mf) {
            uint32_t addr = qsb
                + ((wi * 32 + mf * 16 + (sel & 1) * 8 + l8) * QSTR) * 2
                + kb + (sel >> 1) * 16;
            ldsm_x4(af[mf], addr);
        }
        uint32_t bf[8][2];
#pragma unroll
        for (int np = 0; np < 4; ++np) {
            uint32_t r4[4];
            uint32_t addr = ksb
                + ((np * 16 + (sel >> 1) * 8 + l8) * QSTR) * 2
                + kb + (sel & 1) * 16;
            ldsm_x4(r4, addr);
            bf[np * 2 + 0][0] = r4[0]; bf[np * 2 + 0][1] = r4[1];
            bf[np * 2 + 1][0] = r4[2]; bf[np * 2 + 1][1] = r4[3];
        }
#pragma unroll
        for (int mf = 0; mf < 2; ++mf)
#pragma unroll
            for (int nf = 0; nf < NFT; ++nf)
                mma16816(s[mf][nf], af[mf], bf[nf]);
    }

    float inv[2][2];
#pragma unroll
    for (int mf = 0; mf < 2; ++mf) {
        int rA = wi * 32 + mf * 16 + g;
        int rB = rA + 8;
        int rAc = rA < NTOK ? rA : NTOK - 1;
        int rBc = rB < NTOK ? rB : NTOK - 1;
        int cA = rcnt[rAc], cB = rcnt[rBc];
        float mxA = -1e30f, mxB = -1e30f;
#pragma unroll
        for (int nf = 0; nf < NFT; ++nf) {
#pragma unroll
            for (int e = 0; e < 2; ++e) {
                int j  = nf * 8 + cq * 2 + e;
                int jj = j < NTOK ? j : NTOK - 1;
                float bA = __half2float(Bs[rAc * NTOK + jj]);
                float bB = __half2float(Bs[rBc * NTOK + jj]);
                float mk = (rcnt[jj] != cA) ? -100.f : 0.f;
                float tA = s[mf][nf][e] + bA + mk;
                s[mf][nf][e] = (j < NTOK) ? tA : -1e30f;
                mxA = fmaxf(mxA, s[mf][nf][e]);
                float mk2 = (rcnt[jj] != cB) ? -100.f : 0.f;
                float tB = s[mf][nf][2 + e] + bB + mk2;
                s[mf][nf][2 + e] = (j < NTOK) ? tB : -1e30f;
                mxB = fmaxf(mxB, s[mf][nf][2 + e]);
            }
        }
        mxA = fmaxf(mxA, __shfl_xor_sync(0xffffffff, mxA, 1));
        mxA = fmaxf(mxA, __shfl_xor_sync(0xffffffff, mxA, 2));
        mxB = fmaxf(mxB, __shfl_xor_sync(0xffffffff, mxB, 1));
        mxB = fmaxf(mxB, __shfl_xor_sync(0xffffffff, mxB, 2));
        float smA = 0.f, smB = 0.f;
#pragma unroll
        for (int nf = 0; nf < NFT; ++nf) {
#pragma unroll
            for (int e = 0; e < 2; ++e) {
                float eA = __expf(s[mf][nf][e] - mxA);
                float eB = __expf(s[mf][nf][2 + e] - mxB);
                s[mf][nf][e] = eA;  smA += eA;
                s[mf][nf][2 + e] = eB;  smB += eB;
            }
        }
        smA += __shfl_xor_sync(0xffffffff, smA, 1);
        smA += __shfl_xor_sync(0xffffffff, smA, 2);
        smB += __shfl_xor_sync(0xffffffff, smB, 1);
        smB += __shfl_xor_sync(0xffffffff, smB, 2);
        inv[mf][0] = 1.0f / smA;
        inv[mf][1] = 1.0f / smB;
    }

    float o[2][4][4];
#pragma unroll
    for (int i = 0; i < 2; ++i)
#pragma unroll
        for (int j = 0; j < 4; ++j)
#pragma unroll
            for (int k = 0; k < 4; ++k) o[i][j][k] = 0.f;

#pragma unroll
    for (int kt = 0; kt < 4; ++kt) {
        uint32_t pa[2][4];
#pragma unroll
        for (int mf = 0; mf < 2; ++mf) {
            pa[mf][0] = h2pack(s[mf][2 * kt][0], s[mf][2 * kt][1]);
            pa[mf][1] = h2pack(s[mf][2 * kt][2], s[mf][2 * kt][3]);
            if (2 * kt + 1 < NFT) {
                pa[mf][2] = h2pack(s[mf][2 * kt + 1][0], s[mf][2 * kt + 1][1]);
                pa[mf][3] = h2pack(s[mf][2 * kt + 1][2], s[mf][2 * kt + 1][3]);
            } else {
                pa[mf][2] = 0u;   // cols 56..63: probability exactly 0
                pa[mf][3] = 0u;
            }
        }
        uint32_t bv[4][2];
#pragma unroll
        for (int np = 0; np < 2; ++np) {
            uint32_t r4[4];
            // trans load: lane L -> row kt*16 + (L&15), col halfs np*16 + (L>>4)*8
            uint32_t addr = vsb
                + ((kt * 16 + (lane & 15)) * QSTR) * 2
                + np * 32 + (lane >> 4) * 16;
            ldsm_x4_trans(r4, addr);
            bv[np * 2 + 0][0] = r4[0]; bv[np * 2 + 0][1] = r4[1];
            bv[np * 2 + 1][0] = r4[2]; bv[np * 2 + 1][1] = r4[3];
        }
#pragma unroll
        for (int mf = 0; mf < 2; ++mf)
#pragma unroll
            for (int nf = 0; nf < 4; ++nf)
                mma16816(o[mf][nf], pa[mf], bv[nf]);
    }

#pragma unroll
    for (int mf = 0; mf < 2; ++mf) {
        int rA = wi * 32 + mf * 16 + g;
        int rB = rA + 8;
#pragma unroll
        for (int nf = 0; nf < 4; ++nf) {
            int d = nf * 8 + cq * 2;
            if (rA < NTOK) {
                *(uint32_t*)(gOh + (size_t)(w * NTOK + rA) * CDIM + h * HD + d) =
                    h2pack(o[mf][nf][0] * inv[mf][0], o[mf][nf][1] * inv[mf][0]);
            }
            if (rB < NTOK) {
                *(uint32_t*)(gOh + (size_t)(w * NTOK + rB) * CDIM + h * HD + d) =
                    h2pack(o[mf][nf][2] * inv[mf][1], o[mf][nf][3] * inv[mf][1]);
            }
        }
    }
}

// ---------------- launch ----------------
extern "C" void kernel_launch(void* const* d_in, const int* in_sizes, int n_in,
                              void* d_out, int out_size) {
    (void)in_sizes; (void)n_in; (void)out_size;
    const float* x      = (const float*)d_in[0];
    const float* qkv_w  = (const float*)d_in[1];
    const float* qkv_b  = (const float*)d_in[2];
    const float* proj_w = (const float*)d_in[3];
    const float* proj_b = (const float*)d_in[4];
    const float* rpt    = (const float*)d_in[5];
    float* out = (float*)d_out;

    cudaFuncSetAttribute(mma_gemm, cudaFuncAttributeMaxDynamicSharedMemorySize, SMEM_SZ);

    __half *pXh, *pOh, *pWh, *pPh;
    cudaGetSymbolAddress((void**)&pXh, gXh);
    cudaGetSymbolAddress((void**)&pOh, gOh);
    cudaGetSymbolAddress((void**)&pWh, gWh);
    cudaGetSymbolAddress((void**)&pPh, gPh);

    prep_all<<<(PREP_TOTAL + 255) / 256, 256>>>(rpt, qkv_w, proj_w);
    gather_h<<<(MROWS * (CDIM / 4) + 255) / 256, 256>>>(x);

    dim3 g1(QKVN / TN, MROWS / TM);   // (9, 784)
    mma_gemm<<<g1, 256, SMEM_SZ>>>(pXh, pWh, qkv_b, nullptr, 0);

    attn_mma<<<BW * NHEAD, 64>>>();

    dim3 g2(CDIM / TN, MROWS / TM);   // (3, 784)
    mma_gemm<<<g2, 256, SMEM_SZ>>>(pOh, pPh, proj_b, out, 1);
}

// round 15
// speedup vs baseline: 1.0365x; 1.0365x over previous
#include <cuda_runtime.h>
#include <cuda_fp16.h>
#include <cstdint>

// ---------------- problem constants ----------------
#define B_    8
#define HDIM  112
#define WDIM  112
#define CDIM  384
#define NHEAD 12
#define HD    32
#define WS    7
#define SSH   3
#define NTOK  49
#define NWH   16
#define NWW   16
#define NWIN  256
#define BW    (B_ * NWIN)          // 2048 windows
#define MROWS (BW * NTOK)          // 100352
#define QKVN  (3 * CDIM)           // 1152
#define BSTRIDE 2432

// GEMM tiling: 128x128 CTA tile, 32x64 warp tiles (4Mx2N), 3-stage cp.async
#define TM   128
#define TN   128
#define KC   64
#define NCH  (CDIM / KC)           // 6
#define ROWB 144
#define TILEB (128 * ROWB)         // 18432
#define STAGEB (2 * TILEB)         // 36864
#define NSTAGE 3
#define SMEM_SZ (NSTAGE * STAGEB)  // 110592

// prep fusion ranges
#define NB_BIAS (NHEAD * NTOK * NTOK)    // 28812
#define NW_QKV  (QKVN * CDIM)            // 442368
#define NW_PROJ (CDIM * CDIM)            // 147456
#define PREP_TOTAL (NB_BIAS + NW_QKV + NW_PROJ)

// attention n-tiles: 7 tiles x 8 cols = 56 >= 49 valid cols
#define NFT  7

// ---------------- scratch ----------------
__device__ __half gQh[(size_t)BW * NHEAD * NTOK * HD];
__device__ __half gKh[(size_t)BW * NHEAD * NTOK * HD];
__device__ __half gVh[(size_t)BW * NHEAD * NTOK * HD];
__device__ __half gXh[(size_t)MROWS * CDIM];
__device__ __half gOh[(size_t)MROWS * CDIM];
__device__ __half gWh[(size_t)QKVN * CDIM];
__device__ __half gPh[(size_t)CDIM * CDIM];
__device__ __half gBiasH[NHEAD * BSTRIDE];   // zero-init; tail stays 0

// ---------------- helpers ----------------
#define CP_ASYNC16(dst, src) \
    asm volatile("cp.async.cg.shared.global [%0], [%1], 16;" :: "r"(dst), "l"(src))
#define CP_COMMIT() asm volatile("cp.async.commit_group;" ::: "memory")
#define CP_WAIT(n)  asm volatile("cp.async.wait_group %0;" :: "n"(n) : "memory")

__device__ __forceinline__ uint32_t smem_u32(const void* p) {
    uint32_t a;
    asm("{ .reg .u64 t; cvta.to.shared.u64 t, %1; cvt.u32.u64 %0, t; }" : "=r"(a) : "l"(p));
    return a;
}
__device__ __forceinline__ void ldsm_x4(uint32_t* r, uint32_t addr) {
    asm volatile("ldmatrix.sync.aligned.m8n8.x4.shared.b16 {%0,%1,%2,%3}, [%4];"
                 : "=r"(r[0]), "=r"(r[1]), "=r"(r[2]), "=r"(r[3]) : "r"(addr));
}
__device__ __forceinline__ void ldsm_x4_trans(uint32_t* r, uint32_t addr) {
    asm volatile("ldmatrix.sync.aligned.m8n8.x4.trans.shared.b16 {%0,%1,%2,%3}, [%4];"
                 : "=r"(r[0]), "=r"(r[1]), "=r"(r[2]), "=r"(r[3]) : "r"(addr));
}
__device__ __forceinline__ void mma16816(float* c, const uint32_t* a, const uint32_t* b) {
    asm volatile(
        "mma.sync.aligned.m16n8k16.row.col.f32.f16.f16.f32 "
        "{%0,%1,%2,%3}, {%4,%5,%6,%7}, {%8,%9}, {%0,%1,%2,%3};"
        : "+f"(c[0]), "+f"(c[1]), "+f"(c[2]), "+f"(c[3])
        : "r"(a[0]), "r"(a[1]), "r"(a[2]), "r"(a[3]), "r"(b[0]), "r"(b[1]));
}
__device__ __forceinline__ uint32_t h2pack(float a, float b) {
    __half2 h = __floats2half2_rn(a, b);
    return *reinterpret_cast<uint32_t*>(&h);
}

// ---------------- shift/window row mapping ----------------
__device__ __forceinline__ int src_row(int m) {
    int w  = m / NTOK;
    int n  = m - w * NTOK;
    int b  = w / NWIN;
    int wi = w - b * NWIN;
    int wy = wi / NWW;
    int wx = wi - wy * NWW;
    int ty = n / WS;
    int tx = n - ty * WS;
    int sy = wy * WS + ty;
    int sx = wx * WS + tx;
    int oy = sy + SSH; if (oy >= HDIM) oy -= HDIM;
    int ox = sx + SSH; if (ox >= WDIM) ox -= WDIM;
    return (b * HDIM + oy) * WDIM + ox;
}

// ---------------- prep: fused bias + both weight converts ----------------
__global__ __launch_bounds__(256) void prep_all(const float* __restrict__ rpt,
                                                const float* __restrict__ qkv_w,
                                                const float* __restrict__ proj_w) {
    int t = blockIdx.x * blockDim.x + threadIdx.x;
    if (t < NB_BIAS) {
        int h = t / (NTOK * NTOK);
        int r = t - h * (NTOK * NTOK);
        int i = r / NTOK;
        int j = r - i * NTOK;
        int ci = 13 * (i / 7) + (i % 7);
        int jr = 48 - j;
        int cj = 13 * (jr / 7) + (jr % 7);
        gBiasH[h * BSTRIDE + r] = __float2half_rn(rpt[(ci + cj) * NHEAD + h]);
    } else if (t < NB_BIAS + NW_QKV) {
        int i = t - NB_BIAS;
        int n = i / CDIM;
        int k = i - n * CDIM;
        gWh[i] = __float2half_rn(qkv_w[(size_t)k * QKVN + n]);
    } else if (t < PREP_TOTAL) {
        int i = t - NB_BIAS - NW_QKV;
        int n = i / CDIM;
        int k = i - n * CDIM;
        gPh[i] = __float2half_rn(proj_w[(size_t)k * CDIM + n]);
    }
}

__global__ __launch_bounds__(256) void gather_h(const float* __restrict__ x) {
    int t = blockIdx.x * blockDim.x + threadIdx.x;
    if (t >= MROWS * (CDIM / 4)) return;
    int m = t / (CDIM / 4);
    int q = t - m * (CDIM / 4);
    float4 v = *(const float4*)(x + (size_t)src_row(m) * CDIM + q * 4);
    *(uint2*)(gXh + (size_t)m * CDIM + q * 4) =
        make_uint2(h2pack(v.x, v.y), h2pack(v.z, v.w));
}

// ---------------- HMMA GEMM: C[m,n] = sum_k A[m,k]*B[n,k] + bias[n] --------------
__device__ __forceinline__ void load_stage(uint32_t sbuf, int tid,
        const __half* A, const __half* Bm, int m0, int n0, int k0) {
#pragma unroll
    for (int i = 0; i < 8; ++i) {
        int q    = tid + i * 256;
        int tile = q >> 10;
        int idx  = q & 1023;
        int r    = idx >> 3;
        int c    = idx & 7;
        const __half* srcp = (tile == 0)
            ? A  + (size_t)(m0 + r) * CDIM + k0 + c * 8
            : Bm + (size_t)(n0 + r) * CDIM + k0 + c * 8;
        uint32_t dst = sbuf + tile * TILEB + r * ROWB + c * 16;
        CP_ASYNC16(dst, srcp);
    }
}

__global__ __launch_bounds__(256, 2) void mma_gemm(
        const __half* __restrict__ A, const __half* __restrict__ Bm,
        const float* __restrict__ bias, float* __restrict__ outp, int mode) {
    extern __shared__ char smem[];
    uint32_t sb = smem_u32(smem);

    int tid  = threadIdx.x;
    int wid  = tid >> 5;
    int lane = tid & 31;
    int wm   = wid & 3;
    int wn   = wid >> 2;
    int n0   = blockIdx.x * TN;
    int m0   = blockIdx.y * TM;

    float acc[2][8][4];
#pragma unroll
    for (int i = 0; i < 2; ++i)
#pragma unroll
        for (int j = 0; j < 8; ++j)
#pragma unroll
            for (int k = 0; k < 4; ++k) acc[i][j][k] = 0.f;

    load_stage(sb, tid, A, Bm, m0, n0, 0);
    CP_COMMIT();
    load_stage(sb + STAGEB, tid, A, Bm, m0, n0, KC);
    CP_COMMIT();
    load_stage(sb + 2 * STAGEB, tid, A, Bm, m0, n0, 2 * KC);
    CP_COMMIT();

    int l8  = lane & 7;
    int sel = lane >> 3;
    int g   = lane >> 2;
    int cq  = lane & 3;

#pragma unroll 1
    for (int s = 0; s < NCH; ++s) {
        if (s < NCH - 2)       { CP_WAIT(2); }
        else if (s == NCH - 2) { CP_WAIT(1); }
        else                   { CP_WAIT(0); }
        __syncthreads();
        int bufi = s % NSTAGE;
        uint32_t aBase = sb + bufi * STAGEB;
        uint32_t bBase = aBase + TILEB;

#pragma unroll
        for (int ks = 0; ks < 4; ++ks) {
            int kb = ks * 32;
            uint32_t af[2][4];
#pragma unroll
            for (int mf = 0; mf < 2; ++mf) {
                uint32_t addr = aBase
                    + (wm * 32 + mf * 16 + (sel & 1) * 8 + l8) * ROWB
                    + kb + (sel >> 1) * 16;
                ldsm_x4(af[mf], addr);
            }
            uint32_t bf[8][2];
#pragma unroll
            for (int np = 0; np < 4; ++np) {
                uint32_t r4[4];
                uint32_t addr = bBase
                    + (wn * 64 + np * 16 + (sel >> 1) * 8 + l8) * ROWB
                    + kb + (sel & 1) * 16;
                ldsm_x4(r4, addr);
                bf[np * 2 + 0][0] = r4[0]; bf[np * 2 + 0][1] = r4[1];
                bf[np * 2 + 1][0] = r4[2]; bf[np * 2 + 1][1] = r4[3];
            }
#pragma unroll
            for (int mf = 0; mf < 2; ++mf)
#pragma unroll
                for (int nf = 0; nf < 8; ++nf)
                    mma16816(acc[mf][nf], af[mf], bf[nf]);
        }
        __syncthreads();
        if (s + 3 < NCH) {
            load_stage(sb + bufi * STAGEB, tid, A, Bm, m0, n0, (s + 3) * KC);
            CP_COMMIT();
        }
    }

    const float qscale = 0.17677669529663689f;
#pragma unroll
    for (int mf = 0; mf < 2; ++mf) {
#pragma unroll
        for (int nf = 0; nf < 8; ++nf) {
            int cn   = n0 + wn * 64 + nf * 8 + cq * 2;
            int row0 = m0 + wm * 32 + mf * 16 + g;
            float2 bb = *(const float2*)(bias + cn);
            float v00 = acc[mf][nf][0] + bb.x, v01 = acc[mf][nf][1] + bb.y;
            float v10 = acc[mf][nf][2] + bb.x, v11 = acc[mf][nf][3] + bb.y;
            if (mode == 0) {
                int t   = cn / CDIM;
                int rem = cn - t * CDIM;
                int hh  = rem >> 5;
                int d   = rem & 31;
                __half* basep = (t == 0) ? gQh : (t == 1) ? gKh : gVh;
                float sc = (t == 0) ? qscale : 1.0f;
#pragma unroll
                for (int rr = 0; rr < 2; ++rr) {
                    int m  = row0 + rr * 8;
                    int w  = m / NTOK;
                    int nn = m - w * NTOK;
                    uint32_t hv = (rr == 0) ? h2pack(v00 * sc, v01 * sc)
                                            : h2pack(v10 * sc, v11 * sc);
                    *(uint32_t*)(basep + ((size_t)(w * NHEAD + hh) * NTOK + nn) * HD + d) = hv;
                }
            } else {
#pragma unroll
                for (int rr = 0; rr < 2; ++rr) {
                    int m = row0 + rr * 8;
                    int orow = src_row(m);
                    *(float2*)(outp + (size_t)orow * CDIM + cn) =
                        (rr == 0) ? make_float2(v00, v01) : make_float2(v10, v11);
                }
            }
        }
    }
}

// ---------------- attention: HMMA, 7 n-tiles, cp.async fills --------------------
#define QSTR 40      // Qs/Ks/Vs row stride in halfs
#define NPADR 64

__global__ __launch_bounds__(64) void attn_mma() {
    __shared__ __half Qs[NPADR * QSTR];
    __shared__ __half Ks[NPADR * QSTR];
    __shared__ __half Vs[NPADR * QSTR];
    __shared__ __align__(16) __half Bs[2432];
    __shared__ int    rcnt[NPADR];

    int bid = blockIdx.x;
    int w   = bid / NHEAD;
    int h   = bid - w * NHEAD;
    int tid  = threadIdx.x;
    int wi   = tid >> 5;
    int lane = tid & 31;
    int g    = lane >> 2;
    int cq   = lane & 3;
    int l8   = lane & 7;
    int sel  = lane >> 3;

    size_t base = (size_t)(w * NHEAD + h) * NTOK * HD;
    const uint4* q4 = (const uint4*)(gQh + base);
    const uint4* k4 = (const uint4*)(gKh + base);
    const uint4* v4 = (const uint4*)(gVh + base);

    uint32_t qsb = smem_u32(Qs);
    uint32_t ksb = smem_u32(Ks);
    uint32_t vsb = smem_u32(Vs);
    uint32_t bsb = smem_u32(Bs);

    // ---- cp.async fills (49 valid rows of Q/K/V + bias), no register round-trip -
#pragma unroll
    for (int i = 0; i < 4; ++i) {
        int idx = tid + i * 64;
        if (idx < NTOK * 4) {
            int r = idx >> 2, c = idx & 3;
            uint32_t off = (uint32_t)(r * QSTR * 2 + c * 16);
            CP_ASYNC16(qsb + off, q4 + idx);
            CP_ASYNC16(ksb + off, k4 + idx);
            CP_ASYNC16(vsb + off, v4 + idx);
        }
    }
    const uint4* b4 = (const uint4*)(gBiasH + h * BSTRIDE);
#pragma unroll
    for (int i = 0; i < 5; ++i) {
        int idx = tid + i * 64;
        if (idx < 304) CP_ASYNC16(bsb + idx * 16, b4 + idx);
    }
    CP_COMMIT();

    // ---- independent work while copies fly: V pad-row zeroing + region ids ----
    // (V pad rows are rows >=49 — disjoint from the cp.async target rows <49.)
    {
        uint32_t* vz = (uint32_t*)(Vs + NTOK * QSTR);
#pragma unroll
        for (int i = 0; i < 5; ++i) {
            int idx = tid + i * 64;
            if (idx < 300) vz[idx] = 0;
        }
    }
    if (tid < NPADR) {
        int r = 0;
        if (tid < NTOK) {
            int wpos = w % NWIN;
            int wy = wpos / NWW, wx = wpos - wy * NWW;
            int ty = tid / WS, tx = tid - ty * WS;
            int sy = wy * WS + ty, sx = wx * WS + tx;
            int idh = (sy < HDIM - WS) ? 0 : (sy < HDIM - SSH) ? 1 : 2;
            int idw = (sx < WDIM - WS) ? 0 : (sx < WDIM - SSH) ? 1 : 2;
            r = idh * 3 + idw;
        }
        rcnt[tid] = r;
    }
    CP_WAIT(0);
    __syncthreads();

    float s[2][NFT][4];
#pragma unroll
    for (int i = 0; i < 2; ++i)
#pragma unroll
        for (int j = 0; j < NFT; ++j)
#pragma unroll
            for (int k = 0; k < 4; ++k) s[i][j][k] = 0.f;

#pragma unroll
    for (int ks = 0; ks < 2; ++ks) {
        int kb = ks * 32;
        uint32_t af[2][4];
#pragma unroll
        for (int mf = 0; mf < 2; ++mf) {
            uint32_t addr = qsb
                + ((wi * 32 + mf * 16 + (sel & 1) * 8 + l8) * QSTR) * 2
                + kb + (sel >> 1) * 16;
            ldsm_x4(af[mf], addr);
        }
        uint32_t bf[8][2];
#pragma unroll
        for (int np = 0; np < 4; ++np) {
            uint32_t r4[4];
            uint32_t addr = ksb
                + ((np * 16 + (sel >> 1) * 8 + l8) * QSTR) * 2
                + kb + (sel & 1) * 16;
            ldsm_x4(r4, addr);
            bf[np * 2 + 0][0] = r4[0]; bf[np * 2 + 0][1] = r4[1];
            bf[np * 2 + 1][0] = r4[2]; bf[np * 2 + 1][1] = r4[3];
        }
#pragma unroll
        for (int mf = 0; mf < 2; ++mf)
#pragma unroll
            for (int nf = 0; nf < NFT; ++nf)
                mma16816(s[mf][nf], af[mf], bf[nf]);
    }

    float inv[2][2];
#pragma unroll
    for (int mf = 0; mf < 2; ++mf) {
        int rA = wi * 32 + mf * 16 + g;
        int rB = rA + 8;
        int rAc = rA < NTOK ? rA : NTOK - 1;
        int rBc = rB < NTOK ? rB : NTOK - 1;
        int cA = rcnt[rAc], cB = rcnt[rBc];
        float mxA = -1e30f, mxB = -1e30f;
#pragma unroll
        for (int nf = 0; nf < NFT; ++nf) {
#pragma unroll
            for (int e = 0; e < 2; ++e) {
                int j  = nf * 8 + cq * 2 + e;
                int jj = j < NTOK ? j : NTOK - 1;
                float bA = __half2float(Bs[rAc * NTOK + jj]);
                float bB = __half2float(Bs[rBc * NTOK + jj]);
                float mk = (rcnt[jj] != cA) ? -100.f : 0.f;
                float tA = s[mf][nf][e] + bA + mk;
                s[mf][nf][e] = (j < NTOK) ? tA : -1e30f;
                mxA = fmaxf(mxA, s[mf][nf][e]);
                float mk2 = (rcnt[jj] != cB) ? -100.f : 0.f;
                float tB = s[mf][nf][2 + e] + bB + mk2;
                s[mf][nf][2 + e] = (j < NTOK) ? tB : -1e30f;
                mxB = fmaxf(mxB, s[mf][nf][2 + e]);
            }
        }
        mxA = fmaxf(mxA, __shfl_xor_sync(0xffffffff, mxA, 1));
        mxA = fmaxf(mxA, __shfl_xor_sync(0xffffffff, mxA, 2));
        mxB = fmaxf(mxB, __shfl_xor_sync(0xffffffff, mxB, 1));
        mxB = fmaxf(mxB, __shfl_xor_sync(0xffffffff, mxB, 2));
        float smA = 0.f, smB = 0.f;
#pragma unroll
        for (int nf = 0; nf < NFT; ++nf) {
#pragma unroll
            for (int e = 0; e < 2; ++e) {
                float eA = __expf(s[mf][nf][e] - mxA);
                float eB = __expf(s[mf][nf][2 + e] - mxB);
                s[mf][nf][e] = eA;  smA += eA;
                s[mf][nf][2 + e] = eB;  smB += eB;
            }
        }
        smA += __shfl_xor_sync(0xffffffff, smA, 1);
        smA += __shfl_xor_sync(0xffffffff, smA, 2);
        smB += __shfl_xor_sync(0xffffffff, smB, 1);
        smB += __shfl_xor_sync(0xffffffff, smB, 2);
        inv[mf][0] = 1.0f / smA;
        inv[mf][1] = 1.0f / smB;
    }

    float o[2][4][4];
#pragma unroll
    for (int i = 0; i < 2; ++i)
#pragma unroll
        for (int j = 0; j < 4; ++j)
#pragma unroll
            for (int k = 0; k < 4; ++k) o[i][j][k] = 0.f;

#pragma unroll
    for (int kt = 0; kt < 4; ++kt) {
        uint32_t pa[2][4];
#pragma unroll
        for (int mf = 0; mf < 2; ++mf) {
            pa[mf][0] = h2pack(s[mf][2 * kt][0], s[mf][2 * kt][1]);
            pa[mf][1] = h2pack(s[mf][2 * kt][2], s[mf][2 * kt][3]);
            if (2 * kt + 1 < NFT) {
                pa[mf][2] = h2pack(s[mf][2 * kt + 1][0], s[mf][2 * kt + 1][1]);
                pa[mf][3] = h2pack(s[mf][2 * kt + 1][2], s[mf][2 * kt + 1][3]);
            } else {
                pa[mf][2] = 0u;   // cols 56..63: probability exactly 0
                pa[mf][3] = 0u;
            }
        }
        uint32_t bv[4][2];
#pragma unroll
        for (int np = 0; np < 2; ++np) {
            uint32_t r4[4];
            // trans load: lane L -> row kt*16 + (L&15), col halfs np*16 + (L>>4)*8
            uint32_t addr = vsb
                + ((kt * 16 + (lane & 15)) * QSTR) * 2
                + np * 32 + (lane >> 4) * 16;
            ldsm_x4_trans(r4, addr);
            bv[np * 2 + 0][0] = r4[0]; bv[np * 2 + 0][1] = r4[1];
            bv[np * 2 + 1][0] = r4[2]; bv[np * 2 + 1][1] = r4[3];
        }
#pragma unroll
        for (int mf = 0; mf < 2; ++mf)
#pragma unroll
            for (int nf = 0; nf < 4; ++nf)
                mma16816(o[mf][nf], pa[mf], bv[nf]);
    }

#pragma unroll
    for (int mf = 0; mf < 2; ++mf) {
        int rA = wi * 32 + mf * 16 + g;
        int rB = rA + 8;
#pragma unroll
        for (int nf = 0; nf < 4; ++nf) {
            int d = nf * 8 + cq * 2;
            if (rA < NTOK) {
                *(uint32_t*)(gOh + (size_t)(w * NTOK + rA) * CDIM + h * HD + d) =
                    h2pack(o[mf][nf][0] * inv[mf][0], o[mf][nf][1] * inv[mf][0]);
            }
            if (rB < NTOK) {
                *(uint32_t*)(gOh + (size_t)(w * NTOK + rB) * CDIM + h * HD + d) =
                    h2pack(o[mf][nf][2] * inv[mf][1], o[mf][nf][3] * inv[mf][1]);
            }
        }
    }
}

// ---------------- launch ----------------
extern "C" void kernel_launch(void* const* d_in, const int* in_sizes, int n_in,
                              void* d_out, int out_size) {
    (void)in_sizes; (void)n_in; (void)out_size;
    const float* x      = (const float*)d_in[0];
    const float* qkv_w  = (const float*)d_in[1];
    const float* qkv_b  = (const float*)d_in[2];
    const float* proj_w = (const float*)d_in[3];
    const float* proj_b = (const float*)d_in[4];
    const float* rpt    = (const float*)d_in[5];
    float* out = (float*)d_out;

    cudaFuncSetAttribute(mma_gemm, cudaFuncAttributeMaxDynamicSharedMemorySize, SMEM_SZ);

    __half *pXh, *pOh, *pWh, *pPh;
    cudaGetSymbolAddress((void**)&pXh, gXh);
    cudaGetSymbolAddress((void**)&pOh, gOh);
    cudaGetSymbolAddress((void**)&pWh, gWh);
    cudaGetSymbolAddress((void**)&pPh, gPh);

    prep_all<<<(PREP_TOTAL + 255) / 256, 256>>>(rpt, qkv_w, proj_w);
    gather_h<<<(MROWS * (CDIM / 4) + 255) / 256, 256>>>(x);

    dim3 g1(QKVN / TN, MROWS / TM);   // (9, 784)
    mma_gemm<<<g1, 256, SMEM_SZ>>>(pXh, pWh, qkv_b, nullptr, 0);

    attn_mma<<<BW * NHEAD, 64>>>();

    dim3 g2(CDIM / TN, MROWS / TM);   // (3, 784)
    mma_gemm<<<g2, 256, SMEM_SZ>>>(pOh, pPh, proj_b, out, 1);
}

// round 16
// speedup vs baseline: 1.0515x; 1.0145x over previous
#include <cuda_runtime.h>
#include <cuda_fp16.h>
#include <cstdint>

// ---------------- problem constants ----------------
#define B_    8
#define HDIM  112
#define WDIM  112
#define CDIM  384
#define NHEAD 12
#define HD    32
#define WS    7
#define SSH   3
#define NTOK  49
#define NWH   16
#define NWW   16
#define NWIN  256
#define BW    (B_ * NWIN)          // 2048 windows
#define MROWS (BW * NTOK)          // 100352
#define QKVN  (3 * CDIM)           // 1152
#define BROWS 56                   // bias row stride (halfs, even -> LDS.32 pairs)
#define BHEADS 2816                // bias per-head stride (49*56=2744, pad to 16B mult)

// GEMM tiling: 128x128 CTA tile, 32x64 warp tiles (4Mx2N), 3-stage cp.async
#define TM   128
#define TN   128
#define KC   64
#define NCH  (CDIM / KC)           // 6
#define ROWB 144
#define TILEB (128 * ROWB)         // 18432
#define STAGEB (2 * TILEB)         // 36864
#define NSTAGE 3
#define SMEM_SZ (NSTAGE * STAGEB)  // 110592

// prep fusion ranges (gather + bias + both weight converts in ONE kernel)
#define NGATHER (MROWS * (CDIM / 4))     // 9633792
#define NB_BIAS (NHEAD * NTOK * NTOK)    // 28812
#define NW_QKV  (QKVN * CDIM)            // 442368
#define NW_PROJ (CDIM * CDIM)            // 147456
#define PREP_TOTAL (NGATHER + NB_BIAS + NW_QKV + NW_PROJ)

// attention n-tiles: 7 tiles x 8 cols = 56 >= 49 valid cols
#define NFT  7

// ---------------- scratch ----------------
__device__ __half gQh[(size_t)BW * NHEAD * NTOK * HD];
__device__ __half gKh[(size_t)BW * NHEAD * NTOK * HD];
__device__ __half gVh[(size_t)BW * NHEAD * NTOK * HD];
__device__ __half gXh[(size_t)MROWS * CDIM];
__device__ __half gOh[(size_t)MROWS * CDIM];
__device__ __half gWh[(size_t)QKVN * CDIM];
__device__ __half gPh[(size_t)CDIM * CDIM];
__device__ __half gBiasH[NHEAD * BHEADS];   // zero-init; pad cols stay 0

// ---------------- helpers ----------------
#define CP_ASYNC16(dst, src) \
    asm volatile("cp.async.cg.shared.global [%0], [%1], 16;" :: "r"(dst), "l"(src))
#define CP_COMMIT() asm volatile("cp.async.commit_group;" ::: "memory")
#define CP_WAIT(n)  asm volatile("cp.async.wait_group %0;" :: "n"(n) : "memory")

__device__ __forceinline__ uint32_t smem_u32(const void* p) {
    uint32_t a;
    asm("{ .reg .u64 t; cvta.to.shared.u64 t, %1; cvt.u32.u64 %0, t; }" : "=r"(a) : "l"(p));
    return a;
}
__device__ __forceinline__ void ldsm_x4(uint32_t* r, uint32_t addr) {
    asm volatile("ldmatrix.sync.aligned.m8n8.x4.shared.b16 {%0,%1,%2,%3}, [%4];"
                 : "=r"(r[0]), "=r"(r[1]), "=r"(r[2]), "=r"(r[3]) : "r"(addr));
}
__device__ __forceinline__ void ldsm_x4_trans(uint32_t* r, uint32_t addr) {
    asm volatile("ldmatrix.sync.aligned.m8n8.x4.trans.shared.b16 {%0,%1,%2,%3}, [%4];"
                 : "=r"(r[0]), "=r"(r[1]), "=r"(r[2]), "=r"(r[3]) : "r"(addr));
}
__device__ __forceinline__ void mma16816(float* c, const uint32_t* a, const uint32_t* b) {
    asm volatile(
        "mma.sync.aligned.m16n8k16.row.col.f32.f16.f16.f32 "
        "{%0,%1,%2,%3}, {%4,%5,%6,%7}, {%8,%9}, {%0,%1,%2,%3};"
        : "+f"(c[0]), "+f"(c[1]), "+f"(c[2]), "+f"(c[3])
        : "r"(a[0]), "r"(a[1]), "r"(a[2]), "r"(a[3]), "r"(b[0]), "r"(b[1]));
}
__device__ __forceinline__ uint32_t h2pack(float a, float b) {
    __half2 h = __floats2half2_rn(a, b);
    return *reinterpret_cast<uint32_t*>(&h);
}

// ---------------- shift/window row mapping ----------------
__device__ __forceinline__ int src_row(int m) {
    int w  = m / NTOK;
    int n  = m - w * NTOK;
    int b  = w / NWIN;
    int wi = w - b * NWIN;
    int wy = wi / NWW;
    int wx = wi - wy * NWW;
    int ty = n / WS;
    int tx = n - ty * WS;
    int sy = wy * WS + ty;
    int sx = wx * WS + tx;
    int oy = sy + SSH; if (oy >= HDIM) oy -= HDIM;
    int ox = sx + SSH; if (ox >= WDIM) ox -= WDIM;
    return (b * HDIM + oy) * WDIM + ox;
}

// ---------------- prep: fused gather + bias + both weight converts ----------------
__global__ __launch_bounds__(256) void prep_all(const float* __restrict__ x,
                                                const float* __restrict__ rpt,
                                                const float* __restrict__ qkv_w,
                                                const float* __restrict__ proj_w) {
    int t = blockIdx.x * blockDim.x + threadIdx.x;
    if (t < NGATHER) {
        int m = t / (CDIM / 4);
        int q = t - m * (CDIM / 4);
        float4 v = *(const float4*)(x + (size_t)src_row(m) * CDIM + q * 4);
        *(uint2*)(gXh + (size_t)m * CDIM + q * 4) =
            make_uint2(h2pack(v.x, v.y), h2pack(v.z, v.w));
    } else if (t < NGATHER + NB_BIAS) {
        int u = t - NGATHER;
        int h = u / (NTOK * NTOK);
        int r = u - h * (NTOK * NTOK);
        int i = r / NTOK;
        int j = r - i * NTOK;
        int ci = 13 * (i / 7) + (i % 7);
        int jr = 48 - j;
        int cj = 13 * (jr / 7) + (jr % 7);
        gBiasH[h * BHEADS + i * BROWS + j] = __float2half_rn(rpt[(ci + cj) * NHEAD + h]);
    } else if (t < NGATHER + NB_BIAS + NW_QKV) {
        int i = t - NGATHER - NB_BIAS;
        int n = i / CDIM;
        int k = i - n * CDIM;
        gWh[i] = __float2half_rn(qkv_w[(size_t)k * QKVN + n]);
    } else if (t < PREP_TOTAL) {
        int i = t - NGATHER - NB_BIAS - NW_QKV;
        int n = i / CDIM;
        int k = i - n * CDIM;
        gPh[i] = __float2half_rn(proj_w[(size_t)k * CDIM + n]);
    }
}

// ---------------- HMMA GEMM: C[m,n] = sum_k A[m,k]*B[n,k] + bias[n] --------------
__device__ __forceinline__ void load_stage(uint32_t sbuf, int tid,
        const __half* A, const __half* Bm, int m0, int n0, int k0) {
#pragma unroll
    for (int i = 0; i < 8; ++i) {
        int q    = tid + i * 256;
        int tile = q >> 10;
        int idx  = q & 1023;
        int r    = idx >> 3;
        int c    = idx & 7;
        const __half* srcp = (tile == 0)
            ? A  + (size_t)(m0 + r) * CDIM + k0 + c * 8
            : Bm + (size_t)(n0 + r) * CDIM + k0 + c * 8;
        uint32_t dst = sbuf + tile * TILEB + r * ROWB + c * 16;
        CP_ASYNC16(dst, srcp);
    }
}

__global__ __launch_bounds__(256, 2) void mma_gemm(
        const __half* __restrict__ A, const __half* __restrict__ Bm,
        const float* __restrict__ bias, float* __restrict__ outp, int mode) {
    extern __shared__ char smem[];
    uint32_t sb = smem_u32(smem);

    int tid  = threadIdx.x;
    int wid  = tid >> 5;
    int lane = tid & 31;
    int wm   = wid & 3;
    int wn   = wid >> 2;
    int n0   = blockIdx.x * TN;
    int m0   = blockIdx.y * TM;

    float acc[2][8][4];
#pragma unroll
    for (int i = 0; i < 2; ++i)
#pragma unroll
        for (int j = 0; j < 8; ++j)
#pragma unroll
            for (int k = 0; k < 4; ++k) acc[i][j][k] = 0.f;

    load_stage(sb, tid, A, Bm, m0, n0, 0);
    CP_COMMIT();
    load_stage(sb + STAGEB, tid, A, Bm, m0, n0, KC);
    CP_COMMIT();
    load_stage(sb + 2 * STAGEB, tid, A, Bm, m0, n0, 2 * KC);
    CP_COMMIT();

    int l8  = lane & 7;
    int sel = lane >> 3;
    int g   = lane >> 2;
    int cq  = lane & 3;

#pragma unroll 1
    for (int s = 0; s < NCH; ++s) {
        if (s < NCH - 2)       { CP_WAIT(2); }
        else if (s == NCH - 2) { CP_WAIT(1); }
        else                   { CP_WAIT(0); }
        __syncthreads();
        int bufi = s % NSTAGE;
        uint32_t aBase = sb + bufi * STAGEB;
        uint32_t bBase = aBase + TILEB;

#pragma unroll
        for (int ks = 0; ks < 4; ++ks) {
            int kb = ks * 32;
            uint32_t af[2][4];
#pragma unroll
            for (int mf = 0; mf < 2; ++mf) {
                uint32_t addr = aBase
                    + (wm * 32 + mf * 16 + (sel & 1) * 8 + l8) * ROWB
                    + kb + (sel >> 1) * 16;
                ldsm_x4(af[mf], addr);
            }
            uint32_t bf[8][2];
#pragma unroll
            for (int np = 0; np < 4; ++np) {
                uint32_t r4[4];
                uint32_t addr = bBase
                    + (wn * 64 + np * 16 + (sel >> 1) * 8 + l8) * ROWB
                    + kb + (sel & 1) * 16;
                ldsm_x4(r4, addr);
                bf[np * 2 + 0][0] = r4[0]; bf[np * 2 + 0][1] = r4[1];
                bf[np * 2 + 1][0] = r4[2]; bf[np * 2 + 1][1] = r4[3];
            }
#pragma unroll
            for (int mf = 0; mf < 2; ++mf)
#pragma unroll
                for (int nf = 0; nf < 8; ++nf)
                    mma16816(acc[mf][nf], af[mf], bf[nf]);
        }
        __syncthreads();
        if (s + 3 < NCH) {
            load_stage(sb + bufi * STAGEB, tid, A, Bm, m0, n0, (s + 3) * KC);
            CP_COMMIT();
        }
    }

    const float qscale = 0.17677669529663689f;
#pragma unroll
    for (int mf = 0; mf < 2; ++mf) {
#pragma unroll
        for (int nf = 0; nf < 8; ++nf) {
            int cn   = n0 + wn * 64 + nf * 8 + cq * 2;
            int row0 = m0 + wm * 32 + mf * 16 + g;
            float2 bb = *(const float2*)(bias + cn);
            float v00 = acc[mf][nf][0] + bb.x, v01 = acc[mf][nf][1] + bb.y;
            float v10 = acc[mf][nf][2] + bb.x, v11 = acc[mf][nf][3] + bb.y;
            if (mode == 0) {
                int t   = cn / CDIM;
                int rem = cn - t * CDIM;
                int hh  = rem >> 5;
                int d   = rem & 31;
                __half* basep = (t == 0) ? gQh : (t == 1) ? gKh : gVh;
                float sc = (t == 0) ? qscale : 1.0f;
#pragma unroll
                for (int rr = 0; rr < 2; ++rr) {
                    int m  = row0 + rr * 8;
                    int w  = m / NTOK;
                    int nn = m - w * NTOK;
                    uint32_t hv = (rr == 0) ? h2pack(v00 * sc, v01 * sc)
                                            : h2pack(v10 * sc, v11 * sc);
                    *(uint32_t*)(basep + ((size_t)(w * NHEAD + hh) * NTOK + nn) * HD + d) = hv;
                }
            } else {
#pragma unroll
                for (int rr = 0; rr < 2; ++rr) {
                    int m = row0 + rr * 8;
                    int orow = src_row(m);
                    *(float2*)(outp + (size_t)orow * CDIM + cn) =
                        (rr == 0) ? make_float2(v00, v01) : make_float2(v10, v11);
                }
            }
        }
    }
}

// ---------------- attention: HMMA, branch-free masked softmax -------------------
#define QSTR 40      // Qs/Ks/Vs row stride in halfs
#define NPADR 64

__global__ __launch_bounds__(64) void attn_mma() {
    __shared__ __half Qs[NPADR * QSTR];
    __shared__ __half Ks[NPADR * QSTR];
    __shared__ __half Vs[NPADR * QSTR];
    __shared__ __align__(16) __half Bs[NTOK * BROWS];   // 2744 halfs, 56-stride rows
    __shared__ int    rcnt[NPADR];

    int bid = blockIdx.x;
    int w   = bid / NHEAD;
    int h   = bid - w * NHEAD;
    int tid  = threadIdx.x;
    int wi   = tid >> 5;
    int lane = tid & 31;
    int g    = lane >> 2;
    int cq   = lane & 3;
    int l8   = lane & 7;
    int sel  = lane >> 3;

    size_t base = (size_t)(w * NHEAD + h) * NTOK * HD;
    const uint4* q4 = (const uint4*)(gQh + base);
    const uint4* k4 = (const uint4*)(gKh + base);
    const uint4* v4 = (const uint4*)(gVh + base);

    uint32_t qsb = smem_u32(Qs);
    uint32_t ksb = smem_u32(Ks);
    uint32_t vsb = smem_u32(Vs);
    uint32_t bsb = smem_u32(Bs);

    // ---- cp.async fills (49 valid rows of Q/K/V + bias) ----
#pragma unroll
    for (int i = 0; i < 4; ++i) {
        int idx = tid + i * 64;
        if (idx < NTOK * 4) {
            int r = idx >> 2, c = idx & 3;
            uint32_t off = (uint32_t)(r * QSTR * 2 + c * 16);
            CP_ASYNC16(qsb + off, q4 + idx);
            CP_ASYNC16(ksb + off, k4 + idx);
            CP_ASYNC16(vsb + off, v4 + idx);
        }
    }
    const uint4* b4 = (const uint4*)(gBiasH + h * BHEADS);
#pragma unroll
    for (int i = 0; i < 6; ++i) {
        int idx = tid + i * 64;
        if (idx < 343) CP_ASYNC16(bsb + idx * 16, b4 + idx);   // 2744 halfs = 343 x 16B
    }
    CP_COMMIT();

    // ---- independent: V pad rows 49..63 zero; K pad rows 49..55 zero; rcnt ----
    {
        uint32_t* vz = (uint32_t*)(Vs + NTOK * QSTR);
#pragma unroll
        for (int i = 0; i < 5; ++i) {
            int idx = tid + i * 64;
            if (idx < 300) vz[idx] = 0;
        }
        uint32_t* kz = (uint32_t*)(Ks + NTOK * QSTR);
#pragma unroll
        for (int i = 0; i < 3; ++i) {
            int idx = tid + i * 64;
            if (idx < 140) kz[idx] = 0;    // rows 49..55 (7 rows x 80B)
        }
    }
    if (tid < NPADR) {
        int r = 255;                        // pad rows: never match any region
        if (tid < NTOK) {
            int wpos = w % NWIN;
            int wy = wpos / NWW, wx = wpos - wy * NWW;
            int ty = tid / WS, tx = tid - ty * WS;
            int sy = wy * WS + ty, sx = wx * WS + tx;
            int idh = (sy < HDIM - WS) ? 0 : (sy < HDIM - SSH) ? 1 : 2;
            int idw = (sx < WDIM - WS) ? 0 : (sx < WDIM - SSH) ? 1 : 2;
            r = idh * 3 + idw;
        }
        rcnt[tid] = r;
    }
    CP_WAIT(0);
    __syncthreads();

    float s[2][NFT][4];
#pragma unroll
    for (int i = 0; i < 2; ++i)
#pragma unroll
        for (int j = 0; j < NFT; ++j)
#pragma unroll
            for (int k = 0; k < 4; ++k) s[i][j][k] = 0.f;

#pragma unroll
    for (int ks = 0; ks < 2; ++ks) {
        int kb = ks * 32;
        uint32_t af[2][4];
#pragma unroll
        for (int mf = 0; mf < 2; ++mf) {
            uint32_t addr = qsb
                + ((wi * 32 + mf * 16 + (sel & 1) * 8 + l8) * QSTR) * 2
                + kb + (sel >> 1) * 16;
            ldsm_x4(af[mf], addr);
        }
        uint32_t bf[8][2];
#pragma unroll
        for (int np = 0; np < 4; ++np) {
            uint32_t r4[4];
            uint32_t addr = ksb
                + ((np * 16 + (sel >> 1) * 8 + l8) * QSTR) * 2
                + kb + (sel & 1) * 16;
            ldsm_x4(r4, addr);
            bf[np * 2 + 0][0] = r4[0]; bf[np * 2 + 0][1] = r4[1];
            bf[np * 2 + 1][0] = r4[2]; bf[np * 2 + 1][1] = r4[3];
        }
#pragma unroll
        for (int mf = 0; mf < 2; ++mf)
#pragma unroll
            for (int nf = 0; nf < NFT; ++nf)
                mma16816(s[mf][nf], af[mf], bf[nf]);
    }

    float inv[2][2];
#pragma unroll
    for (int mf = 0; mf < 2; ++mf) {
        int rA = wi * 32 + mf * 16 + g;
        int rB = rA + 8;
        int rAc = rA < NTOK ? rA : NTOK - 1;   // smem row-address clamp only
        int rBc = rB < NTOK ? rB : NTOK - 1;
        int cA = rcnt[rAc], cB = rcnt[rBc];
        const __half* bpA = Bs + rAc * BROWS + cq * 2;
        const __half* bpB = Bs + rBc * BROWS + cq * 2;
        float mxA = -1e30f, mxB = -1e30f;
#pragma unroll
        for (int nf = 0; nf < NFT; ++nf) {
            float2 bA = __half22float2(*(const __half2*)(bpA + nf * 8));
            float2 bB = __half22float2(*(const __half2*)(bpB + nf * 8));
#pragma unroll
            for (int e = 0; e < 2; ++e) {
                int j  = nf * 8 + cq * 2 + e;
                int rj = rcnt[j];
                float bAe = (e == 0) ? bA.x : bA.y;
                float bBe = (e == 0) ? bB.x : bB.y;
                s[mf][nf][e]     += bAe + ((rj != cA) ? -100.f : 0.f);
                s[mf][nf][2 + e] += bBe + ((rj != cB) ? -100.f : 0.f);
                mxA = fmaxf(mxA, s[mf][nf][e]);
                mxB = fmaxf(mxB, s[mf][nf][2 + e]);
            }
        }
        mxA = fmaxf(mxA, __shfl_xor_sync(0xffffffff, mxA, 1));
        mxA = fmaxf(mxA, __shfl_xor_sync(0xffffffff, mxA, 2));
        mxB = fmaxf(mxB, __shfl_xor_sync(0xffffffff, mxB, 1));
        mxB = fmaxf(mxB, __shfl_xor_sync(0xffffffff, mxB, 2));
        float smA = 0.f, smB = 0.f;
#pragma unroll
        for (int nf = 0; nf < NFT; ++nf) {
#pragma unroll
            for (int e = 0; e < 2; ++e) {
                float eA = __expf(s[mf][nf][e] - mxA);
                float eB = __expf(s[mf][nf][2 + e] - mxB);
                s[mf][nf][e] = eA;  smA += eA;
                s[mf][nf][2 + e] = eB;  smB += eB;
            }
        }
        smA += __shfl_xor_sync(0xffffffff, smA, 1);
        smA += __shfl_xor_sync(0xffffffff, smA, 2);
        smB += __shfl_xor_sync(0xffffffff, smB, 1);
        smB += __shfl_xor_sync(0xffffffff, smB, 2);
        inv[mf][0] = 1.0f / smA;
        inv[mf][1] = 1.0f / smB;
    }

    float o[2][4][4];
#pragma unroll
    for (int i = 0; i < 2; ++i)
#pragma unroll
        for (int j = 0; j < 4; ++j)
#pragma unroll
            for (int k = 0; k < 4; ++k) o[i][j][k] = 0.f;

#pragma unroll
    for (int kt = 0; kt < 4; ++kt) {
        uint32_t pa[2][4];
#pragma unroll
        for (int mf = 0; mf < 2; ++mf) {
            pa[mf][0] = h2pack(s[mf][2 * kt][0], s[mf][2 * kt][1]);
            pa[mf][1] = h2pack(s[mf][2 * kt][2], s[mf][2 * kt][3]);
            if (2 * kt + 1 < NFT) {
                pa[mf][2] = h2pack(s[mf][2 * kt + 1][0], s[mf][2 * kt + 1][1]);
                pa[mf][3] = h2pack(s[mf][2 * kt + 1][2], s[mf][2 * kt + 1][3]);
            } else {
                pa[mf][2] = 0u;   // cols 56..63: probability exactly 0
                pa[mf][3] = 0u;
            }
        }
        uint32_t bv[4][2];
#pragma unroll
        for (int np = 0; np < 2; ++np) {
            uint32_t r4[4];
            // trans load: lane L -> row kt*16 + (L&15), col halfs np*16 + (L>>4)*8
            uint32_t addr = vsb
                + ((kt * 16 + (lane & 15)) * QSTR) * 2
                + np * 32 + (lane >> 4) * 16;
            ldsm_x4_trans(r4, addr);
            bv[np * 2 + 0][0] = r4[0]; bv[np * 2 + 0][1] = r4[1];
            bv[np * 2 + 1][0] = r4[2]; bv[np * 2 + 1][1] = r4[3];
        }
#pragma unroll
        for (int mf = 0; mf < 2; ++mf)
#pragma unroll
            for (int nf = 0; nf < 4; ++nf)
                mma16816(o[mf][nf], pa[mf], bv[nf]);
    }

#pragma unroll
    for (int mf = 0; mf < 2; ++mf) {
        int rA = wi * 32 + mf * 16 + g;
        int rB = rA + 8;
#pragma unroll
        for (int nf = 0; nf < 4; ++nf) {
            int d = nf * 8 + cq * 2;
            if (rA < NTOK) {
                *(uint32_t*)(gOh + (size_t)(w * NTOK + rA) * CDIM + h * HD + d) =
                    h2pack(o[mf][nf][0] * inv[mf][0], o[mf][nf][1] * inv[mf][0]);
            }
            if (rB < NTOK) {
                *(uint32_t*)(gOh + (size_t)(w * NTOK + rB) * CDIM + h * HD + d) =
                    h2pack(o[mf][nf][2] * inv[mf][1], o[mf][nf][3] * inv[mf][1]);
            }
        }
    }
}

// ---------------- launch ----------------
extern "C" void kernel_launch(void* const* d_in, const int* in_sizes, int n_in,
                              void* d_out, int out_size) {
    (void)in_sizes; (void)n_in; (void)out_size;
    const float* x      = (const float*)d_in[0];
    const float* qkv_w  = (const float*)d_in[1];
    const float* qkv_b  = (const float*)d_in[2];
    const float* proj_w = (const float*)d_in[3];
    const float* proj_b = (const float*)d_in[4];
    const float* rpt    = (const float*)d_in[5];
    float* out = (float*)d_out;

    cudaFuncSetAttribute(mma_gemm, cudaFuncAttributeMaxDynamicSharedMemorySize, SMEM_SZ);

    __half *pXh, *pOh, *pWh, *pPh;
    cudaGetSymbolAddress((void**)&pXh, gXh);
    cudaGetSymbolAddress((void**)&pOh, gOh);
    cudaGetSymbolAddress((void**)&pWh, gWh);
    cudaGetSymbolAddress((void**)&pPh, gPh);

    prep_all<<<(PREP_TOTAL + 255) / 256, 256>>>(x, rpt, qkv_w, proj_w);

    dim3 g1(QKVN / TN, MROWS / TM);   // (9, 784)
    mma_gemm<<<g1, 256, SMEM_SZ>>>(pXh, pWh, qkv_b, nullptr, 0);

    attn_mma<<<BW * NHEAD, 64>>>();

    dim3 g2(CDIM / TN, MROWS / TM);   // (3, 784)
    mma_gemm<<<g2, 256, SMEM_SZ>>>(pOh, pPh, proj_b, out, 1);
}

// round 17
// speedup vs baseline: 1.0769x; 1.0242x over previous
#include <cuda_runtime.h>
#include <cuda_fp16.h>
#include <cstdint>

// ---------------- problem constants ----------------
#define B_    8
#define HDIM  112
#define WDIM  112
#define CDIM  384
#define NHEAD 12
#define HD    32
#define WS    7
#define SSH   3
#define NTOK  49
#define NWH   16
#define NWW   16
#define NWIN  256
#define BW    (B_ * NWIN)          // 2048 windows
#define MROWS (BW * NTOK)          // 100352
#define QKVN  (3 * CDIM)           // 1152
#define BROWS 56                   // bias row stride (halfs)
#define BHEADS 2816                // bias per-head stride

// GEMM tiling: 128x96 CTA tile, 32x48 warp tiles (4Mx2N), 2-stage, 3 CTAs/SM
#define TM   128
#define TN   96
#define KC   64
#define NCH  (CDIM / KC)           // 6
#define ROWB 144
#define ATILEB (TM * ROWB)         // 18432
#define BTILEB (TN * ROWB)         // 13824
#define STAGEB (ATILEB + BTILEB)   // 32256
#define NSTAGE 2
#define SMEM_SZ (NSTAGE * STAGEB)  // 64512
#define NCHUNK ((TM + TN) * 8)     // 1792 16B chunks per stage

// prep fusion ranges
#define NGATHER (MROWS * (CDIM / 4))     // 9633792
#define NB_BIAS (NHEAD * NTOK * NTOK)    // 28812
#define NW_QKV  (QKVN * CDIM)            // 442368
#define NW_PROJ (CDIM * CDIM)            // 147456
#define PREP_TOTAL (NGATHER + NB_BIAS + NW_QKV + NW_PROJ)

// attention n-tiles
#define NFT  7

// ---------------- scratch ----------------
__device__ __half gQh[(size_t)BW * NHEAD * NTOK * HD];
__device__ __half gKh[(size_t)BW * NHEAD * NTOK * HD];
__device__ __half gVh[(size_t)BW * NHEAD * NTOK * HD];
__device__ __half gXh[(size_t)MROWS * CDIM];
__device__ __half gOh[(size_t)MROWS * CDIM];
__device__ __half gWh[(size_t)QKVN * CDIM];
__device__ __half gPh[(size_t)CDIM * CDIM];
__device__ __half gBiasH[NHEAD * BHEADS];   // zero-init; pad cols stay 0

// ---------------- helpers ----------------
#define CP_ASYNC16(dst, src) \
    asm volatile("cp.async.cg.shared.global [%0], [%1], 16;" :: "r"(dst), "l"(src))
#define CP_COMMIT() asm volatile("cp.async.commit_group;" ::: "memory")
#define CP_WAIT(n)  asm volatile("cp.async.wait_group %0;" :: "n"(n) : "memory")

__device__ __forceinline__ uint32_t smem_u32(const void* p) {
    uint32_t a;
    asm("{ .reg .u64 t; cvta.to.shared.u64 t, %1; cvt.u32.u64 %0, t; }" : "=r"(a) : "l"(p));
    return a;
}
__device__ __forceinline__ void ldsm_x4(uint32_t* r, uint32_t addr) {
    asm volatile("ldmatrix.sync.aligned.m8n8.x4.shared.b16 {%0,%1,%2,%3}, [%4];"
                 : "=r"(r[0]), "=r"(r[1]), "=r"(r[2]), "=r"(r[3]) : "r"(addr));
}
__device__ __forceinline__ void ldsm_x4_trans(uint32_t* r, uint32_t addr) {
    asm volatile("ldmatrix.sync.aligned.m8n8.x4.trans.shared.b16 {%0,%1,%2,%3}, [%4];"
                 : "=r"(r[0]), "=r"(r[1]), "=r"(r[2]), "=r"(r[3]) : "r"(addr));
}
__device__ __forceinline__ void mma16816(float* c, const uint32_t* a, const uint32_t* b) {
    asm volatile(
        "mma.sync.aligned.m16n8k16.row.col.f32.f16.f16.f32 "
        "{%0,%1,%2,%3}, {%4,%5,%6,%7}, {%8,%9}, {%0,%1,%2,%3};"
        : "+f"(c[0]), "+f"(c[1]), "+f"(c[2]), "+f"(c[3])
        : "r"(a[0]), "r"(a[1]), "r"(a[2]), "r"(a[3]), "r"(b[0]), "r"(b[1]));
}
__device__ __forceinline__ uint32_t h2pack(float a, float b) {
    __half2 h = __floats2half2_rn(a, b);
    return *reinterpret_cast<uint32_t*>(&h);
}

// ---------------- shift/window row mapping ----------------
__device__ __forceinline__ int src_row(int m) {
    int w  = m / NTOK;
    int n  = m - w * NTOK;
    int b  = w / NWIN;
    int wi = w - b * NWIN;
    int wy = wi / NWW;
    int wx = wi - wy * NWW;
    int ty = n / WS;
    int tx = n - ty * WS;
    int sy = wy * WS + ty;
    int sx = wx * WS + tx;
    int oy = sy + SSH; if (oy >= HDIM) oy -= HDIM;
    int ox = sx + SSH; if (ox >= WDIM) ox -= WDIM;
    return (b * HDIM + oy) * WDIM + ox;
}

// ---------------- prep: fused gather + bias + both weight converts ----------------
__global__ __launch_bounds__(256) void prep_all(const float* __restrict__ x,
                                                const float* __restrict__ rpt,
                                                const float* __restrict__ qkv_w,
                                                const float* __restrict__ proj_w) {
    int t = blockIdx.x * blockDim.x + threadIdx.x;
    if (t < NGATHER) {
        int m = t / (CDIM / 4);
        int q = t - m * (CDIM / 4);
        float4 v = *(const float4*)(x + (size_t)src_row(m) * CDIM + q * 4);
        *(uint2*)(gXh + (size_t)m * CDIM + q * 4) =
            make_uint2(h2pack(v.x, v.y), h2pack(v.z, v.w));
    } else if (t < NGATHER + NB_BIAS) {
        int u = t - NGATHER;
        int h = u / (NTOK * NTOK);
        int r = u - h * (NTOK * NTOK);
        int i = r / NTOK;
        int j = r - i * NTOK;
        int ci = 13 * (i / 7) + (i % 7);
        int jr = 48 - j;
        int cj = 13 * (jr / 7) + (jr % 7);
        gBiasH[h * BHEADS + i * BROWS + j] = __float2half_rn(rpt[(ci + cj) * NHEAD + h]);
    } else if (t < NGATHER + NB_BIAS + NW_QKV) {
        int i = t - NGATHER - NB_BIAS;
        int n = i / CDIM;
        int k = i - n * CDIM;
        gWh[i] = __float2half_rn(qkv_w[(size_t)k * QKVN + n]);
    } else if (t < PREP_TOTAL) {
        int i = t - NGATHER - NB_BIAS - NW_QKV;
        int n = i / CDIM;
        int k = i - n * CDIM;
        gPh[i] = __float2half_rn(proj_w[(size_t)k * CDIM + n]);
    }
}

// ---------------- HMMA GEMM: C[m,n] = sum_k A[m,k]*B[n,k] + bias[n] --------------
__device__ __forceinline__ void load_stage(uint32_t sbuf, int tid,
        const __half* A, const __half* Bm, int m0, int n0, int k0) {
#pragma unroll
    for (int i = 0; i < 7; ++i) {
        int q = tid + i * 256;               // 1792 chunks
        if (q < TM * 8) {
            int r = q >> 3, c = q & 7;
            CP_ASYNC16(sbuf + r * ROWB + c * 16,
                       A + (size_t)(m0 + r) * CDIM + k0 + c * 8);
        } else {
            int q2 = q - TM * 8;
            int r = q2 >> 3, c = q2 & 7;
            CP_ASYNC16(sbuf + ATILEB + r * ROWB + c * 16,
                       Bm + (size_t)(n0 + r) * CDIM + k0 + c * 8);
        }
    }
}

__global__ __launch_bounds__(256, 3) void mma_gemm(
        const __half* __restrict__ A, const __half* __restrict__ Bm,
        const float* __restrict__ bias, float* __restrict__ outp, int mode) {
    extern __shared__ char smem[];
    uint32_t sb = smem_u32(smem);

    int tid  = threadIdx.x;
    int wid  = tid >> 5;
    int lane = tid & 31;
    int wm   = wid & 3;          // 4 warps over M (32 rows)
    int wn   = wid >> 2;         // 2 warps over N (48 cols)
    int n0   = blockIdx.x * TN;
    int m0   = blockIdx.y * TM;

    float acc[2][6][4];
#pragma unroll
    for (int i = 0; i < 2; ++i)
#pragma unroll
        for (int j = 0; j < 6; ++j)
#pragma unroll
            for (int k = 0; k < 4; ++k) acc[i][j][k] = 0.f;

    load_stage(sb, tid, A, Bm, m0, n0, 0);
    CP_COMMIT();
    load_stage(sb + STAGEB, tid, A, Bm, m0, n0, KC);
    CP_COMMIT();

    int l8  = lane & 7;
    int sel = lane >> 3;
    int g   = lane >> 2;
    int cq  = lane & 3;

#pragma unroll 1
    for (int s = 0; s < NCH; ++s) {
        if (s < NCH - 1) { CP_WAIT(1); } else { CP_WAIT(0); }
        __syncthreads();
        uint32_t aBase = sb + (s & 1) * STAGEB;
        uint32_t bBase = aBase + ATILEB;

#pragma unroll
        for (int ks = 0; ks < 4; ++ks) {
            int kb = ks * 32;
            uint32_t af[2][4];
#pragma unroll
            for (int mf = 0; mf < 2; ++mf) {
                uint32_t addr = aBase
                    + (wm * 32 + mf * 16 + (sel & 1) * 8 + l8) * ROWB
                    + kb + (sel >> 1) * 16;
                ldsm_x4(af[mf], addr);
            }
            uint32_t bf[6][2];
#pragma unroll
            for (int np = 0; np < 3; ++np) {
                uint32_t r4[4];
                uint32_t addr = bBase
                    + (wn * 48 + np * 16 + (sel >> 1) * 8 + l8) * ROWB
                    + kb + (sel & 1) * 16;
                ldsm_x4(r4, addr);
                bf[np * 2 + 0][0] = r4[0]; bf[np * 2 + 0][1] = r4[1];
                bf[np * 2 + 1][0] = r4[2]; bf[np * 2 + 1][1] = r4[3];
            }
#pragma unroll
            for (int mf = 0; mf < 2; ++mf)
#pragma unroll
                for (int nf = 0; nf < 6; ++nf)
                    mma16816(acc[mf][nf], af[mf], bf[nf]);
        }
        __syncthreads();
        if (s + 2 < NCH) {
            load_stage(sb + (s & 1) * STAGEB, tid, A, Bm, m0, n0, (s + 2) * KC);
            CP_COMMIT();
        }
    }

    const float qscale = 0.17677669529663689f;
#pragma unroll
    for (int mf = 0; mf < 2; ++mf) {
#pragma unroll
        for (int nf = 0; nf < 6; ++nf) {
            int cn   = n0 + wn * 48 + nf * 8 + cq * 2;
            int row0 = m0 + wm * 32 + mf * 16 + g;
            float2 bb = *(const float2*)(bias + cn);
            float v00 = acc[mf][nf][0] + bb.x, v01 = acc[mf][nf][1] + bb.y;
            float v10 = acc[mf][nf][2] + bb.x, v11 = acc[mf][nf][3] + bb.y;
            if (mode == 0) {
                int t   = cn / CDIM;
                int rem = cn - t * CDIM;
                int hh  = rem >> 5;
                int d   = rem & 31;
                __half* basep = (t == 0) ? gQh : (t == 1) ? gKh : gVh;
                float sc = (t == 0) ? qscale : 1.0f;
#pragma unroll
                for (int rr = 0; rr < 2; ++rr) {
                    int m  = row0 + rr * 8;
                    int w  = m / NTOK;
                    int nn = m - w * NTOK;
                    uint32_t hv = (rr == 0) ? h2pack(v00 * sc, v01 * sc)
                                            : h2pack(v10 * sc, v11 * sc);
                    *(uint32_t*)(basep + ((size_t)(w * NHEAD + hh) * NTOK + nn) * HD + d) = hv;
                }
            } else {
#pragma unroll
                for (int rr = 0; rr < 2; ++rr) {
                    int m = row0 + rr * 8;
                    int orow = src_row(m);
                    *(float2*)(outp + (size_t)orow * CDIM + cn) =
                        (rr == 0) ? make_float2(v00, v01) : make_float2(v10, v11);
                }
            }
        }
    }
}

// ---------------- attention: HMMA, branch-free masked softmax (R16, committed) ---
#define QSTR 40
#define NPADR 64

__global__ __launch_bounds__(64) void attn_mma() {
    __shared__ __half Qs[NPADR * QSTR];
    __shared__ __half Ks[NPADR * QSTR];
    __shared__ __half Vs[NPADR * QSTR];
    __shared__ __align__(16) __half Bs[NTOK * BROWS];
    __shared__ int    rcnt[NPADR];

    int bid = blockIdx.x;
    int w   = bid / NHEAD;
    int h   = bid - w * NHEAD;
    int tid  = threadIdx.x;
    int wi   = tid >> 5;
    int lane = tid & 31;
    int g    = lane >> 2;
    int cq   = lane & 3;
    int l8   = lane & 7;
    int sel  = lane >> 3;

    size_t base = (size_t)(w * NHEAD + h) * NTOK * HD;
    const uint4* q4 = (const uint4*)(gQh + base);
    const uint4* k4 = (const uint4*)(gKh + base);
    const uint4* v4 = (const uint4*)(gVh + base);

    uint32_t qsb = smem_u32(Qs);
    uint32_t ksb = smem_u32(Ks);
    uint32_t vsb = smem_u32(Vs);
    uint32_t bsb = smem_u32(Bs);

#pragma unroll
    for (int i = 0; i < 4; ++i) {
        int idx = tid + i * 64;
        if (idx < NTOK * 4) {
            int r = idx >> 2, c = idx & 3;
            uint32_t off = (uint32_t)(r * QSTR * 2 + c * 16);
            CP_ASYNC16(qsb + off, q4 + idx);
            CP_ASYNC16(ksb + off, k4 + idx);
            CP_ASYNC16(vsb + off, v4 + idx);
        }
    }
    const uint4* b4 = (const uint4*)(gBiasH + h * BHEADS);
#pragma unroll
    for (int i = 0; i < 6; ++i) {
        int idx = tid + i * 64;
        if (idx < 343) CP_ASYNC16(bsb + idx * 16, b4 + idx);
    }
    CP_COMMIT();

    {
        uint32_t* vz = (uint32_t*)(Vs + NTOK * QSTR);
#pragma unroll
        for (int i = 0; i < 5; ++i) {
            int idx = tid + i * 64;
            if (idx < 300) vz[idx] = 0;
        }
        uint32_t* kz = (uint32_t*)(Ks + NTOK * QSTR);
#pragma unroll
        for (int i = 0; i < 3; ++i) {
            int idx = tid + i * 64;
            if (idx < 140) kz[idx] = 0;
        }
    }
    if (tid < NPADR) {
        int r = 255;
        if (tid < NTOK) {
            int wpos = w % NWIN;
            int wy = wpos / NWW, wx = wpos - wy * NWW;
            int ty = tid / WS, tx = tid - ty * WS;
            int sy = wy * WS + ty, sx = wx * WS + tx;
            int idh = (sy < HDIM - WS) ? 0 : (sy < HDIM - SSH) ? 1 : 2;
            int idw = (sx < WDIM - WS) ? 0 : (sx < WDIM - SSH) ? 1 : 2;
            r = idh * 3 + idw;
        }
        rcnt[tid] = r;
    }
    CP_WAIT(0);
    __syncthreads();

    float s[2][NFT][4];
#pragma unroll
    for (int i = 0; i < 2; ++i)
#pragma unroll
        for (int j = 0; j < NFT; ++j)
#pragma unroll
            for (int k = 0; k < 4; ++k) s[i][j][k] = 0.f;

#pragma unroll
    for (int ks = 0; ks < 2; ++ks) {
        int kb = ks * 32;
        uint32_t af[2][4];
#pragma unroll
        for (int mf = 0; mf < 2; ++mf) {
            uint32_t addr = qsb
                + ((wi * 32 + mf * 16 + (sel & 1) * 8 + l8) * QSTR) * 2
                + kb + (sel >> 1) * 16;
            ldsm_x4(af[mf], addr);
        }
        uint32_t bf[8][2];
#pragma unroll
        for (int np = 0; np < 4; ++np) {
            uint32_t r4[4];
            uint32_t addr = ksb
                + ((np * 16 + (sel >> 1) * 8 + l8) * QSTR) * 2
                + kb + (sel & 1) * 16;
            ldsm_x4(r4, addr);
            bf[np * 2 + 0][0] = r4[0]; bf[np * 2 + 0][1] = r4[1];
            bf[np * 2 + 1][0] = r4[2]; bf[np * 2 + 1][1] = r4[3];
        }
#pragma unroll
        for (int mf = 0; mf < 2; ++mf)
#pragma unroll
            for (int nf = 0; nf < NFT; ++nf)
                mma16816(s[mf][nf], af[mf], bf[nf]);
    }

    float inv[2][2];
#pragma unroll
    for (int mf = 0; mf < 2; ++mf) {
        int rA = wi * 32 + mf * 16 + g;
        int rB = rA + 8;
        int rAc = rA < NTOK ? rA : NTOK - 1;
        int rBc = rB < NTOK ? rB : NTOK - 1;
        int cA = rcnt[rAc], cB = rcnt[rBc];
        const __half* bpA = Bs + rAc * BROWS + cq * 2;
        const __half* bpB = Bs + rBc * BROWS + cq * 2;
        float mxA = -1e30f, mxB = -1e30f;
#pragma unroll
        for (int nf = 0; nf < NFT; ++nf) {
            float2 bA = __half22float2(*(const __half2*)(bpA + nf * 8));
            float2 bB = __half22float2(*(const __half2*)(bpB + nf * 8));
#pragma unroll
            for (int e = 0; e < 2; ++e) {
                int j  = nf * 8 + cq * 2 + e;
                int rj = rcnt[j];
                float bAe = (e == 0) ? bA.x : bA.y;
                float bBe = (e == 0) ? bB.x : bB.y;
                s[mf][nf][e]     += bAe + ((rj != cA) ? -100.f : 0.f);
                s[mf][nf][2 + e] += bBe + ((rj != cB) ? -100.f : 0.f);
                mxA = fmaxf(mxA, s[mf][nf][e]);
                mxB = fmaxf(mxB, s[mf][nf][2 + e]);
            }
        }
        mxA = fmaxf(mxA, __shfl_xor_sync(0xffffffff, mxA, 1));
        mxA = fmaxf(mxA, __shfl_xor_sync(0xffffffff, mxA, 2));
        mxB = fmaxf(mxB, __shfl_xor_sync(0xffffffff, mxB, 1));
        mxB = fmaxf(mxB, __shfl_xor_sync(0xffffffff, mxB, 2));
        float smA = 0.f, smB = 0.f;
#pragma unroll
        for (int nf = 0; nf < NFT; ++nf) {
#pragma unroll
            for (int e = 0; e < 2; ++e) {
                float eA = __expf(s[mf][nf][e] - mxA);
                float eB = __expf(s[mf][nf][2 + e] - mxB);
                s[mf][nf][e] = eA;  smA += eA;
                s[mf][nf][2 + e] = eB;  smB += eB;
            }
        }
        smA += __shfl_xor_sync(0xffffffff, smA, 1);
        smA += __shfl_xor_sync(0xffffffff, smA, 2);
        smB += __shfl_xor_sync(0xffffffff, smB, 1);
        smB += __shfl_xor_sync(0xffffffff, smB, 2);
        inv[mf][0] = 1.0f / smA;
        inv[mf][1] = 1.0f / smB;
    }

    float o[2][4][4];
#pragma unroll
    for (int i = 0; i < 2; ++i)
#pragma unroll
        for (int j = 0; j < 4; ++j)
#pragma unroll
            for (int k = 0; k < 4; ++k) o[i][j][k] = 0.f;

#pragma unroll
    for (int kt = 0; kt < 4; ++kt) {
        uint32_t pa[2][4];
#pragma unroll
        for (int mf = 0; mf < 2; ++mf) {
            pa[mf][0] = h2pack(s[mf][2 * kt][0], s[mf][2 * kt][1]);
            pa[mf][1] = h2pack(s[mf][2 * kt][2], s[mf][2 * kt][3]);
            if (2 * kt + 1 < NFT) {
                pa[mf][2] = h2pack(s[mf][2 * kt + 1][0], s[mf][2 * kt + 1][1]);
                pa[mf][3] = h2pack(s[mf][2 * kt + 1][2], s[mf][2 * kt + 1][3]);
            } else {
                pa[mf][2] = 0u;
                pa[mf][3] = 0u;
            }
        }
        uint32_t bv[4][2];
#pragma unroll
        for (int np = 0; np < 2; ++np) {
            uint32_t r4[4];
            uint32_t addr = vsb
                + ((kt * 16 + (lane & 15)) * QSTR) * 2
                + np * 32 + (lane >> 4) * 16;
            ldsm_x4_trans(r4, addr);
            bv[np * 2 + 0][0] = r4[0]; bv[np * 2 + 0][1] = r4[1];
            bv[np * 2 + 1][0] = r4[2]; bv[np * 2 + 1][1] = r4[3];
        }
#pragma unroll
        for (int mf = 0; mf < 2; ++mf)
#pragma unroll
            for (int nf = 0; nf < 4; ++nf)
                mma16816(o[mf][nf], pa[mf], bv[nf]);
    }

#pragma unroll
    for (int mf = 0; mf < 2; ++mf) {
        int rA = wi * 32 + mf * 16 + g;
        int rB = rA + 8;
#pragma unroll
        for (int nf = 0; nf < 4; ++nf) {
            int d = nf * 8 + cq * 2;
            if (rA < NTOK) {
                *(uint32_t*)(gOh + (size_t)(w * NTOK + rA) * CDIM + h * HD + d) =
                    h2pack(o[mf][nf][0] * inv[mf][0], o[mf][nf][1] * inv[mf][0]);
            }
            if (rB < NTOK) {
                *(uint32_t*)(gOh + (size_t)(w * NTOK + rB) * CDIM + h * HD + d) =
                    h2pack(o[mf][nf][2] * inv[mf][1], o[mf][nf][3] * inv[mf][1]);
            }
        }
    }
}

// ---------------- launch ----------------
extern "C" void kernel_launch(void* const* d_in, const int* in_sizes, int n_in,
                              void* d_out, int out_size) {
    (void)in_sizes; (void)n_in; (void)out_size;
    const float* x      = (const float*)d_in[0];
    const float* qkv_w  = (const float*)d_in[1];
    const float* qkv_b  = (const float*)d_in[2];
    const float* proj_w = (const float*)d_in[3];
    const float* proj_b = (const float*)d_in[4];
    const float* rpt    = (const float*)d_in[5];
    float* out = (float*)d_out;

    cudaFuncSetAttribute(mma_gemm, cudaFuncAttributeMaxDynamicSharedMemorySize, SMEM_SZ);

    __half *pXh, *pOh, *pWh, *pPh;
    cudaGetSymbolAddress((void**)&pXh, gXh);
    cudaGetSymbolAddress((void**)&pOh, gOh);
    cudaGetSymbolAddress((void**)&pWh, gWh);
    cudaGetSymbolAddress((void**)&pPh, gPh);

    prep_all<<<(PREP_TOTAL + 255) / 256, 256>>>(x, rpt, qkv_w, proj_w);

    dim3 g1(QKVN / TN, MROWS / TM);   // (12, 784)
    mma_gemm<<<g1, 256, SMEM_SZ>>>(pXh, pWh, qkv_b, nullptr, 0);

    attn_mma<<<BW * NHEAD, 64>>>();

    dim3 g2(CDIM / TN, MROWS / TM);   // (4, 784)
    mma_gemm<<<g2, 256, SMEM_SZ>>>(pOh, pPh, proj_b, out, 1);
}